// round 9
// baseline (speedup 1.0000x reference)
#include <cuda_runtime.h>
#include <math.h>

// Problem constants
#define NB   4        // batch
#define CCH  256      // channels
#define SSP  2304     // spatial tokens (48*48)
#define NH   4        // heads
#define HD   64       // head dim
// 1/sqrt(64) * log2(e): scores are computed directly in log2 domain so the
// softmax uses exp2f (single EX2) instead of expf.
#define ATTN_SCALE_LOG2E 0.18033688011112042f

// Device scratch (allocation-free rule): Q, K, V, A each (N*NH, S, 64) fp32
__device__ float g_Q[NB * NH * SSP * HD];
__device__ float g_K[NB * NH * SSP * HD];
__device__ float g_V[NB * NH * SSP * HD];
__device__ float g_A[NB * NH * SSP * HD];

// ---------------------------------------------------------------------------
// Packed f32x2 helpers (sm_103a): FFMA2 reachable only via PTX fma.rn.f32x2.
// Per-lane IEEE fp32 semantics — bit-identical to two scalar FFMAs.
// ---------------------------------------------------------------------------
typedef unsigned long long u64;

__device__ __forceinline__ u64 pack2(float lo, float hi) {
    u64 r;
    asm("mov.b64 %0, {%1, %2};"
        : "=l"(r) : "r"(__float_as_uint(lo)), "r"(__float_as_uint(hi)));
    return r;
}
__device__ __forceinline__ u64 bcast2(float v) { return pack2(v, v); }

__device__ __forceinline__ float2 unpack2(u64 v) {
    unsigned lo, hi;
    asm("mov.b64 {%0, %1}, %2;" : "=r"(lo), "=r"(hi) : "l"(v));
    return make_float2(__uint_as_float(lo), __uint_as_float(hi));
}
__device__ __forceinline__ u64 ffma2(u64 a, u64 b, u64 c) {
    u64 d;
    asm("fma.rn.f32x2 %0, %1, %2, %3;" : "=l"(d) : "l"(a), "l"(b), "l"(c));
    return d;
}
__device__ __forceinline__ u64 fmul2(u64 a, u64 b) {
    u64 d;
    asm("mul.rn.f32x2 %0, %1, %2;" : "=l"(d) : "l"(a), "l"(b));
    return d;
}

// ---------------------------------------------------------------------------
// Kernel 1: fused QKV 1x1-conv projection (packed-f32x2 micro-kernel).
//   out[(n*NH+h)*S + s][d] = sum_c W[h*64+d][c] * x[n][c][s] + b[h*64+d]
// 64 s-rows x 64 d-cols per block, 256 threads, 4x4 micro-tile.
// Accumulators packed along s (rows i): accp[p][j] holds rows (2p, 2p+1).
// ---------------------------------------------------------------------------
__global__ __launch_bounds__(256) void qkv_kernel(
    const float* __restrict__ x,
    const float* __restrict__ Wq, const float* __restrict__ bq,
    const float* __restrict__ Wk, const float* __restrict__ bk,
    const float* __restrict__ Wv, const float* __restrict__ bv)
{
    __shared__ float Ws[64][33];   // W tile: [d][k]
    __shared__ float Xs[32][68];   // X tile: [k][s], stride 68 (16B aligned rows)

    const int sb   = blockIdx.x * 64;
    const int head = blockIdx.y;
    const int z    = blockIdx.z;
    const int n    = z & 3;
    const int p    = z >> 2;

    const float* Wm = (p == 0) ? Wq : (p == 1) ? Wk : Wv;
    const float* bm = (p == 0) ? bq : (p == 1) ? bk : bv;
    float* outg     = (p == 0) ? g_Q : (p == 1) ? g_K : g_V;

    const int tid = threadIdx.x;
    const int tx  = tid & 15;
    const int ty  = tid >> 4;
    const int o0  = head * 64;

    const float* xbase = x + (size_t)n * CCH * SSP;

    u64 accp[2][4];
    #pragma unroll
    for (int a = 0; a < 2; a++)
        #pragma unroll
        for (int j = 0; j < 4; j++) accp[a][j] = 0ull;

    for (int c0 = 0; c0 < CCH; c0 += 32) {
        {
            int r = tid >> 2, q = tid & 3;
            const float* wr = Wm + (size_t)(o0 + r) * CCH + c0 + q * 8;
            #pragma unroll
            for (int m = 0; m < 8; m++) Ws[r][q * 8 + m] = wr[m];
        }
        {
            int k = tid >> 3, q = tid & 7;
            const float* xr = xbase + (size_t)(c0 + k) * SSP + sb;
            float4 a = *(const float4*)(xr + q * 4);
            float4 b = *(const float4*)(xr + q * 4 + 32);
            *(float4*)&Xs[k][q * 4]      = a;
            *(float4*)&Xs[k][q * 4 + 32] = b;
        }
        __syncthreads();

        #pragma unroll
        for (int k = 0; k < 32; k++) {
            float2 x01 = *(float2*)&Xs[k][ty * 4];
            float2 x23 = *(float2*)&Xs[k][ty * 4 + 2];
            u64 xp0 = pack2(x01.x, x01.y);
            u64 xp1 = pack2(x23.x, x23.y);
            #pragma unroll
            for (int j = 0; j < 4; j++) {
                u64 wb = bcast2(Ws[tx * 4 + j][k]);
                accp[0][j] = ffma2(xp0, wb, accp[0][j]);
                accp[1][j] = ffma2(xp1, wb, accp[1][j]);
            }
        }
        __syncthreads();
    }

    float bj[4];
    #pragma unroll
    for (int j = 0; j < 4; j++) bj[j] = bm[o0 + tx * 4 + j];

    float* ob = outg + ((size_t)(n * NH + head) * SSP + sb) * HD;
    #pragma unroll
    for (int pp = 0; pp < 2; pp++) {
        float2 u[4];
        #pragma unroll
        for (int j = 0; j < 4; j++) u[j] = unpack2(accp[pp][j]);
        float4 v0, v1;
        v0.x = u[0].x + bj[0]; v0.y = u[1].x + bj[1];
        v0.z = u[2].x + bj[2]; v0.w = u[3].x + bj[3];
        v1.x = u[0].y + bj[0]; v1.y = u[1].y + bj[1];
        v1.z = u[2].y + bj[2]; v1.w = u[3].y + bj[3];
        *(float4*)(ob + (size_t)(ty * 4 + 2 * pp + 0) * HD + tx * 4) = v0;
        *(float4*)(ob + (size_t)(ty * 4 + 2 * pp + 1) * HD + tx * 4) = v1;
    }
}

// ---------------------------------------------------------------------------
// Kernel 2: fused flash attention per (n*NH+h, 64-query block).
// Smem: Qs transposed [k][row] stride 66, Ks [t][k] stride 65 (reused for P),
//       Vs [t][d] stride 64. Total 64*66+64*65+64*64 floats = 49920 B.
// Q pre-scaled by 1/sqrt(d)*log2(e); softmax in exp2 domain.
// K/V tiles are software-pipelined: next tile's LDGs issue before the P@V
// phase and land in registers; STS happens at the next iteration top.
// ---------------------------------------------------------------------------
#define QS_STRIDE 66
#define ATTN_SMEM_FLOATS (64 * QS_STRIDE + 64 * 65 + 64 * 64)

__global__ __launch_bounds__(256) void attn_kernel()
{
    extern __shared__ float smem[];
    float* Qs = smem;                              // [64][66] transposed: [k][row]
    float* Ks = smem + 64 * QS_STRIDE;             // [64][65]  (later holds P)
    float* Vs = smem + 64 * QS_STRIDE + 64 * 65;   // [64][64]

    const int s0 = blockIdx.x * 64;
    const int nh = blockIdx.y;

    const float* Qg = g_Q + ((size_t)nh * SSP + s0) * HD;
    const float* Kg = g_K + (size_t)nh * SSP * HD;
    const float* Vg = g_V + (size_t)nh * SSP * HD;

    const int tid = threadIdx.x;
    const int tx  = tid & 15;
    const int ty  = tid >> 4;
    const int pr  = tid >> 2;      // prefetch row 0..63
    const int pq  = tid & 3;       // prefetch quarter 0..3

    // Load Q tile (64 rows x 64 k), pre-scaled, stored TRANSPOSED: Qs[k][row]
    {
        #pragma unroll
        for (int m = 0; m < 4; m++) {
            int c = (pq + 4 * m) * 4;
            float4 v = *(const float4*)(Qg + (size_t)pr * HD + c);
            Qs[(c + 0) * QS_STRIDE + pr] = v.x * ATTN_SCALE_LOG2E;
            Qs[(c + 1) * QS_STRIDE + pr] = v.y * ATTN_SCALE_LOG2E;
            Qs[(c + 2) * QS_STRIDE + pr] = v.z * ATTN_SCALE_LOG2E;
            Qs[(c + 3) * QS_STRIDE + pr] = v.w * ATTN_SCALE_LOG2E;
        }
    }

    float run_max[4], run_sum[4];
    u64 oaccp[4][2];   // packed over d: pairs (4tx, 4tx+1) and (4tx+2, 4tx+3)
    #pragma unroll
    for (int i = 0; i < 4; i++) {
        run_max[i] = -3.0e38f;
        run_sum[i] = 0.0f;
        oaccp[i][0] = 0ull;
        oaccp[i][1] = 0ull;
    }

    // Prefetch tile 0 into registers (4 float4 of K, 4 float4 of V per thread)
    float4 kreg[4], vreg[4];
    {
        const float* kr = Kg + (size_t)pr * HD;
        const float* vr = Vg + (size_t)pr * HD;
        #pragma unroll
        for (int m = 0; m < 4; m++) {
            int c = (pq + 4 * m) * 4;
            kreg[m] = *(const float4*)(kr + c);
            vreg[m] = *(const float4*)(vr + c);
        }
    }
    __syncthreads();   // Qs visible to all

    for (int t0 = 0; t0 < SSP; t0 += 64) {
        // Commit prefetched K (stride 65) and V (float4, stride 64) to smem
        #pragma unroll
        for (int m = 0; m < 4; m++) {
            int c = (pq + 4 * m) * 4;
            Ks[pr * 65 + c + 0] = kreg[m].x;
            Ks[pr * 65 + c + 1] = kreg[m].y;
            Ks[pr * 65 + c + 2] = kreg[m].z;
            Ks[pr * 65 + c + 3] = kreg[m].w;
            *(float4*)&Vs[pr * 64 + c] = vreg[m];
        }
        __syncthreads();

        // Scores (log2 domain), packed over rows i:
        //   saccp[p][j] lanes = rows (2p, 2p+1); col t = 4tx+j
        u64 saccp[2][4];
        #pragma unroll
        for (int a = 0; a < 2; a++)
            #pragma unroll
            for (int j = 0; j < 4; j++) saccp[a][j] = 0ull;

        #pragma unroll 8
        for (int k = 0; k < 64; k++) {
            float2 q01 = *(float2*)&Qs[k * QS_STRIDE + ty * 4];
            float2 q23 = *(float2*)&Qs[k * QS_STRIDE + ty * 4 + 2];
            u64 qp0 = pack2(q01.x, q01.y);
            u64 qp1 = pack2(q23.x, q23.y);
            #pragma unroll
            for (int j = 0; j < 4; j++) {
                u64 kb = bcast2(Ks[(tx * 4 + j) * 65 + k]);
                saccp[0][j] = ffma2(qp0, kb, saccp[0][j]);
                saccp[1][j] = ffma2(qp1, kb, saccp[1][j]);
            }
        }
        __syncthreads();   // all Ks reads done; safe to overwrite with P

        // Unpack scores to scalars for softmax
        float sacc[4][4];
        #pragma unroll
        for (int a = 0; a < 2; a++)
            #pragma unroll
            for (int j = 0; j < 4; j++) {
                float2 u = unpack2(saccp[a][j]);
                sacc[2 * a + 0][j] = u.x;
                sacc[2 * a + 1][j] = u.y;
            }

        // Online softmax per row, exp2 domain
        #pragma unroll
        for (int i = 0; i < 4; i++) {
            float mx = -3.0e38f;
            #pragma unroll
            for (int j = 0; j < 4; j++)
                mx = fmaxf(mx, sacc[i][j]);
            #pragma unroll
            for (int off = 8; off >= 1; off >>= 1)
                mx = fmaxf(mx, __shfl_xor_sync(0xffffffffu, mx, off));

            float nm   = fmaxf(run_max[i], mx);
            float corr = exp2f(run_max[i] - nm);
            run_max[i] = nm;

            float rs = 0.0f;
            #pragma unroll
            for (int j = 0; j < 4; j++) {
                float pv = exp2f(sacc[i][j] - nm);
                sacc[i][j] = pv;
                rs += pv;
            }
            #pragma unroll
            for (int off = 8; off >= 1; off >>= 1)
                rs += __shfl_xor_sync(0xffffffffu, rs, off);

            run_sum[i] = run_sum[i] * corr + rs;
            u64 cb = bcast2(corr);
            oaccp[i][0] = fmul2(oaccp[i][0], cb);
            oaccp[i][1] = fmul2(oaccp[i][1], cb);

            // stash P in the K buffer
            #pragma unroll
            for (int j = 0; j < 4; j++)
                Ks[(ty * 4 + i) * 65 + tx * 4 + j] = sacc[i][j];
        }
        __syncthreads();

        // Issue next-tile prefetch (registers only — overlaps with P@V below).
        // Out-of-range guard: clamp to tile 0 (valid memory, values unused).
        {
            int tn = (t0 + 64 < SSP) ? (t0 + 64) : 0;
            const float* kr = Kg + (size_t)(tn + pr) * HD;
            const float* vr = Vg + (size_t)(tn + pr) * HD;
            #pragma unroll
            for (int m = 0; m < 4; m++) {
                int c = (pq + 4 * m) * 4;
                kreg[m] = *(const float4*)(kr + c);
                vreg[m] = *(const float4*)(vr + c);
            }
        }

        // O += P @ V, packed over d
        #pragma unroll 8
        for (int t = 0; t < 64; t++) {
            float4 vv = *(float4*)&Vs[t * 64 + tx * 4];
            u64 vp0 = pack2(vv.x, vv.y);
            u64 vp1 = pack2(vv.z, vv.w);
            #pragma unroll
            for (int i = 0; i < 4; i++) {
                u64 pb = bcast2(Ks[(ty * 4 + i) * 65 + t]);
                oaccp[i][0] = ffma2(pb, vp0, oaccp[i][0]);
                oaccp[i][1] = ffma2(pb, vp1, oaccp[i][1]);
            }
        }
        __syncthreads();   // before next tile overwrites Ks/Vs
    }

    // Normalize + store to g_A
    float* Ag = g_A + ((size_t)nh * SSP + s0) * HD;
    #pragma unroll
    for (int i = 0; i < 4; i++) {
        float inv = 1.0f / run_sum[i];
        float2 u0 = unpack2(oaccp[i][0]);
        float2 u1 = unpack2(oaccp[i][1]);
        float4 v;
        v.x = u0.x * inv;
        v.y = u0.y * inv;
        v.z = u1.x * inv;
        v.w = u1.y * inv;
        *(float4*)(Ag + (size_t)(ty * 4 + i) * HD + tx * 4) = v;
    }
}

// ---------------------------------------------------------------------------
// Kernel 3: output projection + bias + residual (packed-f32x2 micro-kernel).
//   out[n][o][s] = sum_c Wo[o][c] * A[c][s] + bo[o] + x[n][o][s]
// Accumulators packed along s (cols j): accp[i][p] holds cols (2p, 2p+1).
// ---------------------------------------------------------------------------
__global__ __launch_bounds__(256) void outproj_kernel(
    const float* __restrict__ x,
    const float* __restrict__ Wo, const float* __restrict__ bo,
    float* __restrict__ out)
{
    __shared__ float Ws[64][33];   // [o][k]
    __shared__ float As[32][66];   // [k][s], stride 66 (8B-aligned float2 rows)

    const int sb = blockIdx.x * 64;
    const int o0 = blockIdx.y * 64;
    const int n  = blockIdx.z;

    const int tid = threadIdx.x;
    const int tx  = tid & 15;
    const int ty  = tid >> 4;

    u64 accp[4][2];
    #pragma unroll
    for (int i = 0; i < 4; i++) { accp[i][0] = 0ull; accp[i][1] = 0ull; }

    for (int c0 = 0; c0 < CCH; c0 += 32) {
        {
            int r = tid >> 2, q = tid & 3;
            const float* wr = Wo + (size_t)(o0 + r) * CCH + c0 + q * 8;
            #pragma unroll
            for (int m = 0; m < 8; m++) Ws[r][q * 8 + m] = wr[m];
        }
        {
            int head = c0 >> 6;
            int dchb = c0 & 63;
            const float* base = g_A + ((size_t)(n * NH + head) * SSP + sb) * HD + dchb;
            int sj = tid >> 2, q = tid & 3;
            #pragma unroll
            for (int half = 0; half < 2; half++) {
                int kq = q + 4 * half;
                float4 v = *(const float4*)(base + (size_t)sj * HD + kq * 4);
                As[kq * 4 + 0][sj] = v.x;
                As[kq * 4 + 1][sj] = v.y;
                As[kq * 4 + 2][sj] = v.z;
                As[kq * 4 + 3][sj] = v.w;
            }
        }
        __syncthreads();

        #pragma unroll
        for (int k = 0; k < 32; k++) {
            float2 a01 = *(float2*)&As[k][tx * 4];
            float2 a23 = *(float2*)&As[k][tx * 4 + 2];
            u64 ap0 = pack2(a01.x, a01.y);
            u64 ap1 = pack2(a23.x, a23.y);
            #pragma unroll
            for (int i = 0; i < 4; i++) {
                u64 wb = bcast2(Ws[ty * 4 + i][k]);
                accp[i][0] = ffma2(wb, ap0, accp[i][0]);
                accp[i][1] = ffma2(wb, ap1, accp[i][1]);
            }
        }
        __syncthreads();
    }

    // Epilogue: bias + residual, float4 along s
    #pragma unroll
    for (int i = 0; i < 4; i++) {
        int o = o0 + ty * 4 + i;
        float b = bo[o];
        const float* xr   = x   + ((size_t)n * CCH + o) * SSP + sb + tx * 4;
        float*       orow = out + ((size_t)n * CCH + o) * SSP + sb + tx * 4;
        float4 xv = *(const float4*)xr;
        float2 u0 = unpack2(accp[i][0]);
        float2 u1 = unpack2(accp[i][1]);
        float4 v;
        v.x = u0.x + b + xv.x;
        v.y = u0.y + b + xv.y;
        v.z = u1.x + b + xv.z;
        v.w = u1.y + b + xv.w;
        *(float4*)orow = v;
    }
}

// ---------------------------------------------------------------------------
extern "C" void kernel_launch(void* const* d_in, const int* in_sizes, int n_in,
                              void* d_out, int out_size)
{
    const float* x  = (const float*)d_in[0];
    const float* Wq = (const float*)d_in[1];
    const float* bq = (const float*)d_in[2];
    const float* Wk = (const float*)d_in[3];
    const float* bk = (const float*)d_in[4];
    const float* Wv = (const float*)d_in[5];
    const float* bv = (const float*)d_in[6];
    const float* Wo = (const float*)d_in[7];
    const float* bo = (const float*)d_in[8];
    float* out = (float*)d_out;

    // Opt in to >48KB dynamic smem for the attention kernel (idempotent).
    static const size_t attn_smem = ATTN_SMEM_FLOATS * sizeof(float);
    cudaFuncSetAttribute(attn_kernel,
                         cudaFuncAttributeMaxDynamicSharedMemorySize,
                         (int)attn_smem);

    dim3 g1(SSP / 64, NH, 3 * NB);       // (36, 4, 12)
    qkv_kernel<<<g1, 256>>>(x, Wq, bq, Wk, bk, Wv, bv);

    dim3 g2(SSP / 64, NB * NH);          // (36, 16)
    attn_kernel<<<g2, 256, attn_smem>>>();

    dim3 g3(SSP / 64, CCH / 64, NB);     // (36, 4, 4)
    outproj_kernel<<<g3, 256>>>(x, Wo, bo, out);
}

// round 11
// speedup vs baseline: 1.0527x; 1.0527x over previous
#include <cuda_runtime.h>
#include <math.h>

// Problem constants
#define NB   4        // batch
#define CCH  256      // channels
#define SSP  2304     // spatial tokens (48*48)
#define NH   4        // heads
#define HD   64       // head dim
#define ATTN_SCALE_LOG2E 0.18033688011112042f  // 1/sqrt(64) * log2(e)

// Device scratch (allocation-free rule): Q, K, V, A each (N*NH, S, 64) fp32
__device__ float g_Q[NB * NH * SSP * HD];
__device__ float g_K[NB * NH * SSP * HD];
__device__ float g_V[NB * NH * SSP * HD];
__device__ float g_A[NB * NH * SSP * HD];

// ---------------------------------------------------------------------------
// Packed f32x2 helpers (sm_103a): FFMA2 via PTX fma.rn.f32x2.
// ---------------------------------------------------------------------------
typedef unsigned long long u64;

__device__ __forceinline__ u64 pack2(float lo, float hi) {
    u64 r;
    asm("mov.b64 %0, {%1, %2};"
        : "=l"(r) : "r"(__float_as_uint(lo)), "r"(__float_as_uint(hi)));
    return r;
}
__device__ __forceinline__ u64 bcast2(float v) { return pack2(v, v); }

__device__ __forceinline__ float2 unpack2(u64 v) {
    unsigned lo, hi;
    asm("mov.b64 {%0, %1}, %2;" : "=r"(lo), "=r"(hi) : "l"(v));
    return make_float2(__uint_as_float(lo), __uint_as_float(hi));
}
__device__ __forceinline__ u64 ffma2(u64 a, u64 b, u64 c) {
    u64 d;
    asm("fma.rn.f32x2 %0, %1, %2, %3;" : "=l"(d) : "l"(a), "l"(b), "l"(c));
    return d;
}
__device__ __forceinline__ u64 fmul2(u64 a, u64 b) {
    u64 d;
    asm("mul.rn.f32x2 %0, %1, %2;" : "=l"(d) : "l"(a), "l"(b));
    return d;
}

// ---------------------------------------------------------------------------
// Kernel 1: fused QKV projection. W tile stored TRANSPOSED [k][d] so the
// inner loop is 2x LDS.128 (one X float4, one W float4) per 8 FFMA2.
// ---------------------------------------------------------------------------
__global__ __launch_bounds__(256) void qkv_kernel(
    const float* __restrict__ x,
    const float* __restrict__ Wq, const float* __restrict__ bq,
    const float* __restrict__ Wk, const float* __restrict__ bk,
    const float* __restrict__ Wv, const float* __restrict__ bv)
{
    __shared__ float Ws[32][68];   // W tile TRANSPOSED: [k][d], 16B-aligned rows
    __shared__ float Xs[32][68];   // X tile: [k][s]

    const int sb   = blockIdx.x * 64;
    const int head = blockIdx.y;
    const int z    = blockIdx.z;
    const int n    = z & 3;
    const int p    = z >> 2;

    const float* Wm = (p == 0) ? Wq : (p == 1) ? Wk : Wv;
    const float* bm = (p == 0) ? bq : (p == 1) ? bk : bv;
    float* outg     = (p == 0) ? g_Q : (p == 1) ? g_K : g_V;

    const int tid = threadIdx.x;
    const int tx  = tid & 15;
    const int ty  = tid >> 4;
    const int o0  = head * 64;

    const float* xbase = x + (size_t)n * CCH * SSP;

    u64 accp[2][4];   // packed over rows s (pairs), j = d columns
    #pragma unroll
    for (int a = 0; a < 2; a++)
        #pragma unroll
        for (int j = 0; j < 4; j++) accp[a][j] = 0ull;

    for (int c0 = 0; c0 < CCH; c0 += 32) {
        // W tile 64(d) x 32(k) from global, stored transposed [k][d]
        {
            int r = tid >> 2, q = tid & 3;           // r = d row, q*8.. = k cols
            const float* wr = Wm + (size_t)(o0 + r) * CCH + c0 + q * 8;
            #pragma unroll
            for (int m = 0; m < 8; m++) Ws[q * 8 + m][r] = wr[m];
        }
        // X tile 32(k) x 64(s), float4 stores
        {
            int k = tid >> 3, q = tid & 7;
            const float* xr = xbase + (size_t)(c0 + k) * SSP + sb;
            float4 a = *(const float4*)(xr + q * 4);
            float4 b = *(const float4*)(xr + q * 4 + 32);
            *(float4*)&Xs[k][q * 4]      = a;
            *(float4*)&Xs[k][q * 4 + 32] = b;
        }
        __syncthreads();

        #pragma unroll
        for (int k = 0; k < 32; k++) {
            float4 xv = *(float4*)&Xs[k][ty * 4];    // rows: one LDS.128
            float4 wv = *(float4*)&Ws[k][tx * 4];    // cols: one LDS.128
            u64 xp0 = pack2(xv.x, xv.y);
            u64 xp1 = pack2(xv.z, xv.w);
            u64 wb0 = bcast2(wv.x), wb1 = bcast2(wv.y);
            u64 wb2 = bcast2(wv.z), wb3 = bcast2(wv.w);
            accp[0][0] = ffma2(xp0, wb0, accp[0][0]);
            accp[1][0] = ffma2(xp1, wb0, accp[1][0]);
            accp[0][1] = ffma2(xp0, wb1, accp[0][1]);
            accp[1][1] = ffma2(xp1, wb1, accp[1][1]);
            accp[0][2] = ffma2(xp0, wb2, accp[0][2]);
            accp[1][2] = ffma2(xp1, wb2, accp[1][2]);
            accp[0][3] = ffma2(xp0, wb3, accp[0][3]);
            accp[1][3] = ffma2(xp1, wb3, accp[1][3]);
        }
        __syncthreads();
    }

    float bj[4];
    #pragma unroll
    for (int j = 0; j < 4; j++) bj[j] = bm[o0 + tx * 4 + j];

    float* ob = outg + ((size_t)(n * NH + head) * SSP + sb) * HD;
    #pragma unroll
    for (int pp = 0; pp < 2; pp++) {
        float2 u[4];
        #pragma unroll
        for (int j = 0; j < 4; j++) u[j] = unpack2(accp[pp][j]);
        float4 v0, v1;
        v0.x = u[0].x + bj[0]; v0.y = u[1].x + bj[1];
        v0.z = u[2].x + bj[2]; v0.w = u[3].x + bj[3];
        v1.x = u[0].y + bj[0]; v1.y = u[1].y + bj[1];
        v1.z = u[2].y + bj[2]; v1.w = u[3].y + bj[3];
        *(float4*)(ob + (size_t)(ty * 4 + 2 * pp + 0) * HD + tx * 4) = v0;
        *(float4*)(ob + (size_t)(ty * 4 + 2 * pp + 1) * HD + tx * 4) = v1;
    }
}

// ---------------------------------------------------------------------------
// Kernel 2: fused flash attention per (n*NH+h, 64-query block).
// Qs [k][row] stride 68, Ks TRANSPOSED [k][t] stride 68 (reused for P at
// stride 65), Vs [t][d] stride 64. QK inner loop = 2x LDS.128 per 8 FFMA2.
// K/V software-pipelined through registers across tiles.
// ---------------------------------------------------------------------------
#define QS_STRIDE 68
#define KS_STRIDE 68
#define ATTN_SMEM_FLOATS (64 * QS_STRIDE + 64 * KS_STRIDE + 64 * 64)

__global__ __launch_bounds__(256) void attn_kernel()
{
    extern __shared__ float smem[];
    float* Qs = smem;                                  // [64][68]: [k][row]
    float* Ks = smem + 64 * QS_STRIDE;                 // [64][68]: [k][t]; P at stride 65
    float* Vs = smem + 64 * QS_STRIDE + 64 * KS_STRIDE;// [64][64]: [t][d]

    const int s0 = blockIdx.x * 64;
    const int nh = blockIdx.y;

    const float* Qg = g_Q + ((size_t)nh * SSP + s0) * HD;
    const float* Kg = g_K + (size_t)nh * SSP * HD;
    const float* Vg = g_V + (size_t)nh * SSP * HD;

    const int tid = threadIdx.x;
    const int tx  = tid & 15;
    const int ty  = tid >> 4;
    const int pr  = tid >> 2;      // load row 0..63
    const int pq  = tid & 3;       // load quarter 0..3

    // Load Q tile, pre-scaled, stored TRANSPOSED: Qs[k][row]
    {
        #pragma unroll
        for (int m = 0; m < 4; m++) {
            int c = (pq + 4 * m) * 4;
            float4 v = *(const float4*)(Qg + (size_t)pr * HD + c);
            Qs[(c + 0) * QS_STRIDE + pr] = v.x * ATTN_SCALE_LOG2E;
            Qs[(c + 1) * QS_STRIDE + pr] = v.y * ATTN_SCALE_LOG2E;
            Qs[(c + 2) * QS_STRIDE + pr] = v.z * ATTN_SCALE_LOG2E;
            Qs[(c + 3) * QS_STRIDE + pr] = v.w * ATTN_SCALE_LOG2E;
        }
    }

    float run_max[4], run_sum[4];
    u64 oaccp[4][2];
    #pragma unroll
    for (int i = 0; i < 4; i++) {
        run_max[i] = -3.0e38f;
        run_sum[i] = 0.0f;
        oaccp[i][0] = 0ull;
        oaccp[i][1] = 0ull;
    }

    // Prefetch tile 0 into registers
    float4 kreg[4], vreg[4];
    {
        const float* kr = Kg + (size_t)pr * HD;
        const float* vr = Vg + (size_t)pr * HD;
        #pragma unroll
        for (int m = 0; m < 4; m++) {
            int c = (pq + 4 * m) * 4;
            kreg[m] = *(const float4*)(kr + c);
            vreg[m] = *(const float4*)(vr + c);
        }
    }
    __syncthreads();   // Qs visible

    for (int t0 = 0; t0 < SSP; t0 += 64) {
        // Commit prefetched tiles: K transposed [k][t], V rows [t][d]
        #pragma unroll
        for (int m = 0; m < 4; m++) {
            int c = (pq + 4 * m) * 4;
            Ks[(c + 0) * KS_STRIDE + pr] = kreg[m].x;
            Ks[(c + 1) * KS_STRIDE + pr] = kreg[m].y;
            Ks[(c + 2) * KS_STRIDE + pr] = kreg[m].z;
            Ks[(c + 3) * KS_STRIDE + pr] = kreg[m].w;
            *(float4*)&Vs[pr * 64 + c] = vreg[m];
        }
        __syncthreads();

        // Scores (log2 domain): per k, 2x LDS.128 + 8 FFMA2
        u64 saccp[2][4];
        #pragma unroll
        for (int a = 0; a < 2; a++)
            #pragma unroll
            for (int j = 0; j < 4; j++) saccp[a][j] = 0ull;

        #pragma unroll 8
        for (int k = 0; k < 64; k++) {
            float4 qv = *(float4*)&Qs[k * QS_STRIDE + ty * 4];
            float4 kv = *(float4*)&Ks[k * KS_STRIDE + tx * 4];
            u64 qp0 = pack2(qv.x, qv.y);
            u64 qp1 = pack2(qv.z, qv.w);
            u64 kb0 = bcast2(kv.x), kb1 = bcast2(kv.y);
            u64 kb2 = bcast2(kv.z), kb3 = bcast2(kv.w);
            saccp[0][0] = ffma2(qp0, kb0, saccp[0][0]);
            saccp[1][0] = ffma2(qp1, kb0, saccp[1][0]);
            saccp[0][1] = ffma2(qp0, kb1, saccp[0][1]);
            saccp[1][1] = ffma2(qp1, kb1, saccp[1][1]);
            saccp[0][2] = ffma2(qp0, kb2, saccp[0][2]);
            saccp[1][2] = ffma2(qp1, kb2, saccp[1][2]);
            saccp[0][3] = ffma2(qp0, kb3, saccp[0][3]);
            saccp[1][3] = ffma2(qp1, kb3, saccp[1][3]);
        }
        __syncthreads();   // all Ks reads done; safe to overwrite with P

        float sacc[4][4];
        #pragma unroll
        for (int a = 0; a < 2; a++)
            #pragma unroll
            for (int j = 0; j < 4; j++) {
                float2 u = unpack2(saccp[a][j]);
                sacc[2 * a + 0][j] = u.x;
                sacc[2 * a + 1][j] = u.y;
            }

        // Online softmax per row, exp2 domain
        #pragma unroll
        for (int i = 0; i < 4; i++) {
            float mx = -3.0e38f;
            #pragma unroll
            for (int j = 0; j < 4; j++)
                mx = fmaxf(mx, sacc[i][j]);
            #pragma unroll
            for (int off = 8; off >= 1; off >>= 1)
                mx = fmaxf(mx, __shfl_xor_sync(0xffffffffu, mx, off));

            float nm   = fmaxf(run_max[i], mx);
            float corr = exp2f(run_max[i] - nm);
            run_max[i] = nm;

            float rs = 0.0f;
            #pragma unroll
            for (int j = 0; j < 4; j++) {
                float pv = exp2f(sacc[i][j] - nm);
                sacc[i][j] = pv;
                rs += pv;
            }
            #pragma unroll
            for (int off = 8; off >= 1; off >>= 1)
                rs += __shfl_xor_sync(0xffffffffu, rs, off);

            run_sum[i] = run_sum[i] * corr + rs;
            u64 cb = bcast2(corr);
            oaccp[i][0] = fmul2(oaccp[i][0], cb);
            oaccp[i][1] = fmul2(oaccp[i][1], cb);

            // stash P into the K buffer as [row][t], stride 65
            #pragma unroll
            for (int j = 0; j < 4; j++)
                Ks[(ty * 4 + i) * 65 + tx * 4 + j] = sacc[i][j];
        }
        __syncthreads();

        // Next-tile prefetch (registers only; overlaps with P@V)
        {
            int tn = (t0 + 64 < SSP) ? (t0 + 64) : 0;
            const float* kr = Kg + (size_t)(tn + pr) * HD;
            const float* vr = Vg + (size_t)(tn + pr) * HD;
            #pragma unroll
            for (int m = 0; m < 4; m++) {
                int c = (pq + 4 * m) * 4;
                kreg[m] = *(const float4*)(kr + c);
                vreg[m] = *(const float4*)(vr + c);
            }
        }

        // O += P @ V
        #pragma unroll 8
        for (int t = 0; t < 64; t++) {
            float4 vv = *(float4*)&Vs[t * 64 + tx * 4];
            u64 vp0 = pack2(vv.x, vv.y);
            u64 vp1 = pack2(vv.z, vv.w);
            #pragma unroll
            for (int i = 0; i < 4; i++) {
                u64 pb = bcast2(Ks[(ty * 4 + i) * 65 + t]);
                oaccp[i][0] = ffma2(pb, vp0, oaccp[i][0]);
                oaccp[i][1] = ffma2(pb, vp1, oaccp[i][1]);
            }
        }
        __syncthreads();   // before next tile overwrites Ks/Vs
    }

    // Normalize + store to g_A
    float* Ag = g_A + ((size_t)nh * SSP + s0) * HD;
    #pragma unroll
    for (int i = 0; i < 4; i++) {
        float inv = 1.0f / run_sum[i];
        float2 u0 = unpack2(oaccp[i][0]);
        float2 u1 = unpack2(oaccp[i][1]);
        float4 v;
        v.x = u0.x * inv;
        v.y = u0.y * inv;
        v.z = u1.x * inv;
        v.w = u1.y * inv;
        *(float4*)(Ag + (size_t)(ty * 4 + i) * HD + tx * 4) = v;
    }
}

// ---------------------------------------------------------------------------
// Kernel 3: output projection + bias + residual. Ws transposed [k][o];
// inner loop = 2x LDS.128 per 8 FFMA2.
// ---------------------------------------------------------------------------
__global__ __launch_bounds__(256) void outproj_kernel(
    const float* __restrict__ x,
    const float* __restrict__ Wo, const float* __restrict__ bo,
    float* __restrict__ out)
{
    __shared__ float Ws[32][68];   // TRANSPOSED [k][o]
    __shared__ float As[32][68];   // [k][s]

    const int sb = blockIdx.x * 64;
    const int o0 = blockIdx.y * 64;
    const int n  = blockIdx.z;

    const int tid = threadIdx.x;
    const int tx  = tid & 15;
    const int ty  = tid >> 4;

    u64 accp[4][2];   // rows o (i), packed over s cols (pairs)
    #pragma unroll
    for (int i = 0; i < 4; i++) { accp[i][0] = 0ull; accp[i][1] = 0ull; }

    for (int c0 = 0; c0 < CCH; c0 += 32) {
        // W tile transposed [k][o]
        {
            int r = tid >> 2, q = tid & 3;
            const float* wr = Wo + (size_t)(o0 + r) * CCH + c0 + q * 8;
            #pragma unroll
            for (int m = 0; m < 8; m++) Ws[q * 8 + m][r] = wr[m];
        }
        // A tile 32(k) x 64(s), transposed load from g_A (head-major layout)
        {
            int head = c0 >> 6;
            int dchb = c0 & 63;
            const float* base = g_A + ((size_t)(n * NH + head) * SSP + sb) * HD + dchb;
            int sj = tid >> 2, q = tid & 3;
            #pragma unroll
            for (int half = 0; half < 2; half++) {
                int kq = q + 4 * half;
                float4 v = *(const float4*)(base + (size_t)sj * HD + kq * 4);
                As[kq * 4 + 0][sj] = v.x;
                As[kq * 4 + 1][sj] = v.y;
                As[kq * 4 + 2][sj] = v.z;
                As[kq * 4 + 3][sj] = v.w;
            }
        }
        __syncthreads();

        #pragma unroll
        for (int k = 0; k < 32; k++) {
            float4 av = *(float4*)&As[k][tx * 4];
            float4 wv = *(float4*)&Ws[k][ty * 4];
            u64 ap0 = pack2(av.x, av.y);
            u64 ap1 = pack2(av.z, av.w);
            u64 wb0 = bcast2(wv.x), wb1 = bcast2(wv.y);
            u64 wb2 = bcast2(wv.z), wb3 = bcast2(wv.w);
            accp[0][0] = ffma2(wb0, ap0, accp[0][0]);
            accp[0][1] = ffma2(wb0, ap1, accp[0][1]);
            accp[1][0] = ffma2(wb1, ap0, accp[1][0]);
            accp[1][1] = ffma2(wb1, ap1, accp[1][1]);
            accp[2][0] = ffma2(wb2, ap0, accp[2][0]);
            accp[2][1] = ffma2(wb2, ap1, accp[2][1]);
            accp[3][0] = ffma2(wb3, ap0, accp[3][0]);
            accp[3][1] = ffma2(wb3, ap1, accp[3][1]);
        }
        __syncthreads();
    }

    // Epilogue: bias + residual, float4 along s
    #pragma unroll
    for (int i = 0; i < 4; i++) {
        int o = o0 + ty * 4 + i;
        float b = bo[o];
        const float* xr   = x   + ((size_t)n * CCH + o) * SSP + sb + tx * 4;
        float*       orow = out + ((size_t)n * CCH + o) * SSP + sb + tx * 4;
        float4 xv = *(const float4*)xr;
        float2 u0 = unpack2(accp[i][0]);
        float2 u1 = unpack2(accp[i][1]);
        float4 v;
        v.x = u0.x + b + xv.x;
        v.y = u0.y + b + xv.y;
        v.z = u1.x + b + xv.z;
        v.w = u1.y + b + xv.w;
        *(float4*)orow = v;
    }
}

// ---------------------------------------------------------------------------
extern "C" void kernel_launch(void* const* d_in, const int* in_sizes, int n_in,
                              void* d_out, int out_size)
{
    const float* x  = (const float*)d_in[0];
    const float* Wq = (const float*)d_in[1];
    const float* bq = (const float*)d_in[2];
    const float* Wk = (const float*)d_in[3];
    const float* bk = (const float*)d_in[4];
    const float* Wv = (const float*)d_in[5];
    const float* bv = (const float*)d_in[6];
    const float* Wo = (const float*)d_in[7];
    const float* bo = (const float*)d_in[8];
    float* out = (float*)d_out;

    static const size_t attn_smem = ATTN_SMEM_FLOATS * sizeof(float);
    cudaFuncSetAttribute(attn_kernel,
                         cudaFuncAttributeMaxDynamicSharedMemorySize,
                         (int)attn_smem);

    dim3 g1(SSP / 64, NH, 3 * NB);       // (36, 4, 12)
    qkv_kernel<<<g1, 256>>>(x, Wq, bq, Wk, bk, Wv, bv);

    dim3 g2(SSP / 64, NB * NH);          // (36, 16)
    attn_kernel<<<g2, 256, attn_smem>>>();

    dim3 g3(SSP / 64, CCH / 64, NB);     // (36, 4, 4)
    outproj_kernel<<<g3, 256>>>(x, Wo, bo, out);
}